// round 6
// baseline (speedup 1.0000x reference)
#include <cuda_runtime.h>
#include <cstdint>

#define NNODES 2048
#define JDIM   768      // F_IN * T = 32*24
#define KCHEB  3
#define BATCH  16
#define FOUT   64
#define TDIM   24

// 302 MB scratch: rhs[b][m][k][f*24+t]   (b*2048+m)*2304 + k*768 + f*24 + t
__device__ float g_rhs[(size_t)BATCH * NNODES * KCHEB * JDIM];

__device__ __forceinline__ uint32_t f2tf(float f) {
    uint32_t u;
    asm("cvt.rna.tf32.f32 %0, %1;" : "=r"(u) : "f"(f));
    return u;
}

__device__ __forceinline__ void mma_tf32(float d[4], const uint32_t a[4], const uint32_t b[2]) {
    asm("mma.sync.aligned.m16n8k8.row.col.f32.tf32.tf32.f32 "
        "{%0,%1,%2,%3}, {%4,%5,%6,%7}, {%8,%9}, {%0,%1,%2,%3};"
        : "+f"(d[0]), "+f"(d[1]), "+f"(d[2]), "+f"(d[3])
        : "r"(a[0]), "r"(a[1]), "r"(a[2]), "r"(a[3]),
          "r"(b[0]), "r"(b[1]));
}

// ---------------------------------------------------------------------------
// Stage 1: per (k,b): rhs[m, j] = sum_n (cheb[k][n][m] * att[b][n][m]) * x[b][n][j]
// CTA tile 128(m) x 128(j), K-chunk 32(n). 256 threads = 8 warps (4x2),
// warp tile 32x64 -> 2 m-frags x 8 n-frags of m16n8k8 tf32 mma.
// ---------------------------------------------------------------------------
__global__ void __launch_bounds__(256)
stage1_kernel(const float* __restrict__ x,
              const float* __restrict__ att,
              const float* __restrict__ cheb)
{
    const int k  = blockIdx.z % KCHEB;
    const int b  = blockIdx.z / KCHEB;
    const int m0 = blockIdx.y << 7;
    const int j0 = blockIdx.x << 7;

    const float* __restrict__ Ac = cheb + (size_t)k * NNODES * NNODES;
    const float* __restrict__ Aa = att  + (size_t)b * NNODES * NNODES;
    const float* __restrict__ Xp = x    + (size_t)b * NNODES * JDIM;

    // padded to 136 words: fragment-read stride mod 32 == 8 -> conflict-free
    __shared__ uint32_t As[32][136];   // As[n][m]  (tf32 of cheb*att)
    __shared__ uint32_t Bs[32][136];   // Bs[n][j]  (tf32 of x)

    const int tid  = threadIdx.x;
    const int lane = tid & 31;
    const int warp = tid >> 5;
    const int wm = (warp >> 1) << 5;   // 0,32,64,96
    const int wn = (warp & 1) << 6;    // 0,64
    const int g  = lane >> 2;          // 0..7
    const int ti = lane & 3;           // 0..3

    float acc[2][8][4];
#pragma unroll
    for (int i = 0; i < 2; ++i)
#pragma unroll
        for (int j = 0; j < 8; ++j)
#pragma unroll
            for (int c = 0; c < 4; ++c) acc[i][j][c] = 0.0f;

    float4 rc[4], ra[4], rx[4];

    auto load_tile = [&](int n0) {
#pragma unroll
        for (int i = 0; i < 4; ++i) {
            const int l  = tid + (i << 8);
            const int nr = l >> 5;        // 0..31  (n within chunk)
            const int c4 = l & 31;        // float4 column
            const size_t roA = (size_t)(n0 + nr) * NNODES + m0;
            rc[i] = *(reinterpret_cast<const float4*>(Ac + roA) + c4);
            ra[i] = *(reinterpret_cast<const float4*>(Aa + roA) + c4);
            rx[i] = *(reinterpret_cast<const float4*>(Xp + (size_t)(n0 + nr) * JDIM + j0) + c4);
        }
    };

    auto store_tile = [&]() {
#pragma unroll
        for (int i = 0; i < 4; ++i) {
            const int l  = tid + (i << 8);
            const int nr = l >> 5;
            const int c4 = l & 31;
            uint4 ua, ub;
            ua.x = f2tf(rc[i].x * ra[i].x);
            ua.y = f2tf(rc[i].y * ra[i].y);
            ua.z = f2tf(rc[i].z * ra[i].z);
            ua.w = f2tf(rc[i].w * ra[i].w);
            ub.x = f2tf(rx[i].x);
            ub.y = f2tf(rx[i].y);
            ub.z = f2tf(rx[i].z);
            ub.w = f2tf(rx[i].w);
            *reinterpret_cast<uint4*>(&As[nr][c4 << 2]) = ua;
            *reinterpret_cast<uint4*>(&Bs[nr][c4 << 2]) = ub;
        }
    };

    auto compute = [&]() {
#pragma unroll
        for (int s = 0; s < 4; ++s) {          // 4 k-steps of 8 within the 32-chunk
            const int ks = s << 3;
            uint32_t af[2][4], bf[8][2];
#pragma unroll
            for (int i = 0; i < 2; ++i) {
                const int mi = wm + (i << 4);
                af[i][0] = As[ks + ti][mi + g];
                af[i][1] = As[ks + ti][mi + g + 8];
                af[i][2] = As[ks + ti + 4][mi + g];
                af[i][3] = As[ks + ti + 4][mi + g + 8];
            }
#pragma unroll
            for (int j = 0; j < 8; ++j) {
                const int nj = wn + (j << 3);
                bf[j][0] = Bs[ks + ti][nj + g];
                bf[j][1] = Bs[ks + ti + 4][nj + g];
            }
#pragma unroll
            for (int i = 0; i < 2; ++i)
#pragma unroll
                for (int j = 0; j < 8; ++j)
                    mma_tf32(acc[i][j], af[i], bf[j]);
        }
    };

    load_tile(0);
    store_tile();
    __syncthreads();

    for (int n0 = 0; n0 < NNODES; n0 += 32) {
        const bool has_next = (n0 + 32) < NNODES;
        if (has_next) load_tile(n0 + 32);   // LDGs in flight during compute
        compute();
        __syncthreads();
        if (has_next) {
            store_tile();
            __syncthreads();
        }
    }

    // Epilogue: acc layout c0:(g,2ti) c1:(g,2ti+1) c2:(g+8,2ti) c3:(g+8,2ti+1)
#pragma unroll
    for (int i = 0; i < 2; ++i) {
#pragma unroll
        for (int h = 0; h < 2; ++h) {
            const int row = m0 + wm + (i << 4) + g + (h << 3);
            float* orow = g_rhs
                        + (((size_t)b * NNODES + row) * KCHEB + k) * JDIM
                        + j0 + wn + (ti << 1);
#pragma unroll
            for (int j = 0; j < 8; ++j) {
                float2 v = make_float2(acc[i][j][h << 1], acc[i][j][(h << 1) + 1]);
                *reinterpret_cast<float2*>(orow + (j << 3)) = v;
            }
        }
    }
}

// ---------------------------------------------------------------------------
// Stage 2: out[b,m,o,t] = relu( sum_{k,f} rhs[b,m,k,f,t] * Theta[k,f,o] )
// 128 threads per CTA handle 2 (b,m) pairs; per pair 64 threads cover
// 64(o) x 24(t) in 4x6 register blocks. fp32, FMA-bound.
// ---------------------------------------------------------------------------
__global__ void __launch_bounds__(128)
stage2_kernel(const float* __restrict__ Theta, float* __restrict__ out)
{
    __shared__ float sW[KCHEB * 32 * FOUT];   // 6144 floats, layout [kf][o]
    __shared__ float sR[2 * KCHEB * JDIM];    // 2 x 2304 floats, layout [kf][t]

    const int tid = threadIdx.x;

#pragma unroll
    for (int i = 0; i < 12; ++i) {
        const int l = (tid + (i << 7)) << 2;
        *reinterpret_cast<float4*>(&sW[l]) =
            *reinterpret_cast<const float4*>(Theta + l);
    }
    const size_t bm0 = (size_t)blockIdx.x << 1;
    const float* rbase = g_rhs + bm0 * (KCHEB * JDIM);
#pragma unroll
    for (int i = 0; i < 9; ++i) {
        const int l = (tid + (i << 7)) << 2;
        *reinterpret_cast<float4*>(&sR[l]) =
            *reinterpret_cast<const float4*>(rbase + l);
    }
    __syncthreads();

    const int sub = tid >> 6;            // which (b,m) of the pair
    const int t64 = tid & 63;
    const int o0  = (t64 & 15) << 2;     // 4 consecutive o per thread
    const int tb  = (t64 >> 4) * 6;      // 6 consecutive t per thread
    const float* R = &sR[sub * (KCHEB * JDIM)];

    float acc[4][6];
#pragma unroll
    for (int i = 0; i < 4; ++i)
#pragma unroll
        for (int j = 0; j < 6; ++j) acc[i][j] = 0.0f;

#pragma unroll 4
    for (int kf = 0; kf < 96; ++kf) {
        const float4 w = *reinterpret_cast<const float4*>(&sW[(kf << 6) + o0]);
        const float* rr = &R[kf * TDIM + tb];
#pragma unroll
        for (int j = 0; j < 6; ++j) {
            const float rv = rr[j];
            acc[0][j] = fmaf(w.x, rv, acc[0][j]);
            acc[1][j] = fmaf(w.y, rv, acc[1][j]);
            acc[2][j] = fmaf(w.z, rv, acc[2][j]);
            acc[3][j] = fmaf(w.w, rv, acc[3][j]);
        }
    }

    float* obase = out + (bm0 + sub) * (FOUT * TDIM);
#pragma unroll
    for (int i = 0; i < 4; ++i) {
        float* orow = obase + (o0 + i) * TDIM + tb;
#pragma unroll
        for (int j = 0; j < 6; j += 2) {
            float2 v = make_float2(fmaxf(acc[i][j],     0.0f),
                                   fmaxf(acc[i][j + 1], 0.0f));
            *reinterpret_cast<float2*>(orow + j) = v;
        }
    }
}

// ---------------------------------------------------------------------------
extern "C" void kernel_launch(void* const* d_in, const int* in_sizes, int n_in,
                              void* d_out, int out_size)
{
    (void)in_sizes; (void)n_in; (void)out_size;
    const float* x     = (const float*)d_in[0];   // (16,2048,32,24)
    const float* att   = (const float*)d_in[1];   // (16,2048,2048)
    const float* cheb  = (const float*)d_in[2];   // (3,2048,2048)
    const float* Theta = (const float*)d_in[3];   // (3,32,64)
    float* out = (float*)d_out;                   // (16,2048,64,24)

    dim3 g1(JDIM / 128, NNODES / 128, KCHEB * BATCH);   // (6, 16, 48)
    stage1_kernel<<<g1, 256>>>(x, att, cheb);
    stage2_kernel<<<(BATCH * NNODES) / 2, 128>>>(Theta, out);
}

// round 7
// speedup vs baseline: 1.0002x; 1.0002x over previous
#include <cuda_runtime.h>
#include <cstdint>

#define NNODES 2048
#define JDIM   768      // F_IN * T = 32*24
#define KCHEB  3
#define BATCH  16
#define FOUT   64
#define TDIM   24

// 302 MB scratch: rhs[b][m][k][f*24+t]   (b*2048+m)*2304 + k*768 + f*24 + t
__device__ float g_rhs[(size_t)BATCH * NNODES * KCHEB * JDIM];

__device__ __forceinline__ uint32_t f2tf(float f) {
    uint32_t u;
    asm("cvt.rna.tf32.f32 %0, %1;" : "=r"(u) : "f"(f));
    return u;
}

__device__ __forceinline__ void mma_tf32(float d[4], const uint32_t a[4], const uint32_t b[2]) {
    asm("mma.sync.aligned.m16n8k8.row.col.f32.tf32.tf32.f32 "
        "{%0,%1,%2,%3}, {%4,%5,%6,%7}, {%8,%9}, {%0,%1,%2,%3};"
        : "+f"(d[0]), "+f"(d[1]), "+f"(d[2]), "+f"(d[3])
        : "r"(a[0]), "r"(a[1]), "r"(a[2]), "r"(a[3]),
          "r"(b[0]), "r"(b[1]));
}

// ---------------------------------------------------------------------------
// Stage 1: per (k,b): rhs[m, j] = sum_n (cheb[k][n][m] * att[b][n][m]) * x[b][n][j]
// CTA tile 128(m) x 128(j), K-chunk 32(n). 256 threads = 8 warps (4x2),
// warp tile 32x64 -> 2 m-frags x 8 n-frags of m16n8k8 tf32 mma.
// ---------------------------------------------------------------------------
__global__ void __launch_bounds__(256)
stage1_kernel(const float* __restrict__ x,
              const float* __restrict__ att,
              const float* __restrict__ cheb)
{
    const int k  = blockIdx.z % KCHEB;
    const int b  = blockIdx.z / KCHEB;
    const int m0 = blockIdx.y << 7;
    const int j0 = blockIdx.x << 7;

    const float* __restrict__ Ac = cheb + (size_t)k * NNODES * NNODES;
    const float* __restrict__ Aa = att  + (size_t)b * NNODES * NNODES;
    const float* __restrict__ Xp = x    + (size_t)b * NNODES * JDIM;

    // padded to 136 words: fragment-read stride mod 32 == 8 -> conflict-free
    __shared__ uint32_t As[32][136];   // As[n][m]  (tf32 of cheb*att)
    __shared__ uint32_t Bs[32][136];   // Bs[n][j]  (tf32 of x)

    const int tid  = threadIdx.x;
    const int lane = tid & 31;
    const int warp = tid >> 5;
    const int wm = (warp >> 1) << 5;   // 0,32,64,96
    const int wn = (warp & 1) << 6;    // 0,64
    const int g  = lane >> 2;          // 0..7
    const int ti = lane & 3;           // 0..3

    float acc[2][8][4];
#pragma unroll
    for (int i = 0; i < 2; ++i)
#pragma unroll
        for (int j = 0; j < 8; ++j)
#pragma unroll
            for (int c = 0; c < 4; ++c) acc[i][j][c] = 0.0f;

    float4 rc[4], ra[4], rx[4];

    auto load_tile = [&](int n0) {
#pragma unroll
        for (int i = 0; i < 4; ++i) {
            const int l  = tid + (i << 8);
            const int nr = l >> 5;        // 0..31  (n within chunk)
            const int c4 = l & 31;        // float4 column
            const size_t roA = (size_t)(n0 + nr) * NNODES + m0;
            rc[i] = *(reinterpret_cast<const float4*>(Ac + roA) + c4);
            ra[i] = *(reinterpret_cast<const float4*>(Aa + roA) + c4);
            rx[i] = *(reinterpret_cast<const float4*>(Xp + (size_t)(n0 + nr) * JDIM + j0) + c4);
        }
    };

    auto store_tile = [&]() {
#pragma unroll
        for (int i = 0; i < 4; ++i) {
            const int l  = tid + (i << 8);
            const int nr = l >> 5;
            const int c4 = l & 31;
            uint4 ua, ub;
            ua.x = f2tf(rc[i].x * ra[i].x);
            ua.y = f2tf(rc[i].y * ra[i].y);
            ua.z = f2tf(rc[i].z * ra[i].z);
            ua.w = f2tf(rc[i].w * ra[i].w);
            ub.x = f2tf(rx[i].x);
            ub.y = f2tf(rx[i].y);
            ub.z = f2tf(rx[i].z);
            ub.w = f2tf(rx[i].w);
            *reinterpret_cast<uint4*>(&As[nr][c4 << 2]) = ua;
            *reinterpret_cast<uint4*>(&Bs[nr][c4 << 2]) = ub;
        }
    };

    auto compute = [&]() {
#pragma unroll
        for (int s = 0; s < 4; ++s) {          // 4 k-steps of 8 within the 32-chunk
            const int ks = s << 3;
            uint32_t af[2][4], bf[8][2];
#pragma unroll
            for (int i = 0; i < 2; ++i) {
                const int mi = wm + (i << 4);
                af[i][0] = As[ks + ti][mi + g];
                af[i][1] = As[ks + ti][mi + g + 8];
                af[i][2] = As[ks + ti + 4][mi + g];
                af[i][3] = As[ks + ti + 4][mi + g + 8];
            }
#pragma unroll
            for (int j = 0; j < 8; ++j) {
                const int nj = wn + (j << 3);
                bf[j][0] = Bs[ks + ti][nj + g];
                bf[j][1] = Bs[ks + ti + 4][nj + g];
            }
#pragma unroll
            for (int i = 0; i < 2; ++i)
#pragma unroll
                for (int j = 0; j < 8; ++j)
                    mma_tf32(acc[i][j], af[i], bf[j]);
        }
    };

    load_tile(0);
    store_tile();
    __syncthreads();

    for (int n0 = 0; n0 < NNODES; n0 += 32) {
        const bool has_next = (n0 + 32) < NNODES;
        if (has_next) load_tile(n0 + 32);   // LDGs in flight during compute
        compute();
        __syncthreads();
        if (has_next) {
            store_tile();
            __syncthreads();
        }
    }

    // Epilogue: acc layout c0:(g,2ti) c1:(g,2ti+1) c2:(g+8,2ti) c3:(g+8,2ti+1)
#pragma unroll
    for (int i = 0; i < 2; ++i) {
#pragma unroll
        for (int h = 0; h < 2; ++h) {
            const int row = m0 + wm + (i << 4) + g + (h << 3);
            float* orow = g_rhs
                        + (((size_t)b * NNODES + row) * KCHEB + k) * JDIM
                        + j0 + wn + (ti << 1);
#pragma unroll
            for (int j = 0; j < 8; ++j) {
                float2 v = make_float2(acc[i][j][h << 1], acc[i][j][(h << 1) + 1]);
                *reinterpret_cast<float2*>(orow + (j << 3)) = v;
            }
        }
    }
}

// ---------------------------------------------------------------------------
// Stage 2: out[b,m,o,t] = relu( sum_{k,f} rhs[b,m,k,f,t] * Theta[k,f,o] )
// 128 threads per CTA handle 2 (b,m) pairs; per pair 64 threads cover
// 64(o) x 24(t) in 4x6 register blocks. fp32, FMA-bound.
// ---------------------------------------------------------------------------
__global__ void __launch_bounds__(128)
stage2_kernel(const float* __restrict__ Theta, float* __restrict__ out)
{
    __shared__ float sW[KCHEB * 32 * FOUT];   // 6144 floats, layout [kf][o]
    __shared__ float sR[2 * KCHEB * JDIM];    // 2 x 2304 floats, layout [kf][t]

    const int tid = threadIdx.x;

#pragma unroll
    for (int i = 0; i < 12; ++i) {
        const int l = (tid + (i << 7)) << 2;
        *reinterpret_cast<float4*>(&sW[l]) =
            *reinterpret_cast<const float4*>(Theta + l);
    }
    const size_t bm0 = (size_t)blockIdx.x << 1;
    const float* rbase = g_rhs + bm0 * (KCHEB * JDIM);
#pragma unroll
    for (int i = 0; i < 9; ++i) {
        const int l = (tid + (i << 7)) << 2;
        *reinterpret_cast<float4*>(&sR[l]) =
            *reinterpret_cast<const float4*>(rbase + l);
    }
    __syncthreads();

    const int sub = tid >> 6;            // which (b,m) of the pair
    const int t64 = tid & 63;
    const int o0  = (t64 & 15) << 2;     // 4 consecutive o per thread
    const int tb  = (t64 >> 4) * 6;      // 6 consecutive t per thread
    const float* R = &sR[sub * (KCHEB * JDIM)];

    float acc[4][6];
#pragma unroll
    for (int i = 0; i < 4; ++i)
#pragma unroll
        for (int j = 0; j < 6; ++j) acc[i][j] = 0.0f;

#pragma unroll 4
    for (int kf = 0; kf < 96; ++kf) {
        const float4 w = *reinterpret_cast<const float4*>(&sW[(kf << 6) + o0]);
        const float* rr = &R[kf * TDIM + tb];
#pragma unroll
        for (int j = 0; j < 6; ++j) {
            const float rv = rr[j];
            acc[0][j] = fmaf(w.x, rv, acc[0][j]);
            acc[1][j] = fmaf(w.y, rv, acc[1][j]);
            acc[2][j] = fmaf(w.z, rv, acc[2][j]);
            acc[3][j] = fmaf(w.w, rv, acc[3][j]);
        }
    }

    float* obase = out + (bm0 + sub) * (FOUT * TDIM);
#pragma unroll
    for (int i = 0; i < 4; ++i) {
        float* orow = obase + (o0 + i) * TDIM + tb;
#pragma unroll
        for (int j = 0; j < 6; j += 2) {
            float2 v = make_float2(fmaxf(acc[i][j],     0.0f),
                                   fmaxf(acc[i][j + 1], 0.0f));
            *reinterpret_cast<float2*>(orow + j) = v;
        }
    }
}

// ---------------------------------------------------------------------------
extern "C" void kernel_launch(void* const* d_in, const int* in_sizes, int n_in,
                              void* d_out, int out_size)
{
    (void)in_sizes; (void)n_in; (void)out_size;
    const float* x     = (const float*)d_in[0];   // (16,2048,32,24)
    const float* att   = (const float*)d_in[1];   // (16,2048,2048)
    const float* cheb  = (const float*)d_in[2];   // (3,2048,2048)
    const float* Theta = (const float*)d_in[3];   // (3,32,64)
    float* out = (float*)d_out;                   // (16,2048,64,24)

    dim3 g1(JDIM / 128, NNODES / 128, KCHEB * BATCH);   // (6, 16, 48)
    stage1_kernel<<<g1, 256>>>(x, att, cheb);
    stage2_kernel<<<(BATCH * NNODES) / 2, 128>>>(Theta, out);
}